// round 6
// baseline (speedup 1.0000x reference)
#include <cuda_runtime.h>

// GAE reverse scan, 3-pass chunked linear recurrence.
//   adv_t = delta_t + c_t * adv_{t+1},  c_t = GL*(1-done_{t+1})
//   delta_t = r_t + GAMMA*v_{t+1}*(1-done_{t+1}) - v_t   (v_T=0, done_T=1)
// Output: d_out[0:T*N] = advantages, d_out[T*N:2*T*N] = advantages + values.
//
// R6: maximize resident warps (scalar, 32-reg, 8 blocks/SM, 2048 blocks) and
// keep inputs L2-resident for pass2 via streaming stores/loads.

#define T_DIM   2048
#define N_DIM   4096
#define CT      128                 // chunks in time
#define LCH     (T_DIM / CT)        // 16 rows per chunk
#define BLOCK   256
#define NGRP    (N_DIM / BLOCK)     // 16 column groups -> 2048 blocks

#define GAMMA_F 0.99f
#define GL_F    (0.99f * 0.95f)

// Scratch: per-(chunk, column) affine aggregate (A,B) and carries. 6 MB.
__device__ float2 g_AB   [CT * N_DIM];
__device__ float  g_carry[CT * N_DIM];

// ---------------------------------------------------------------------------
// Pass 1: per-chunk affine reduction. adv_top = A + B * carry_in.
// ---------------------------------------------------------------------------
__global__ __launch_bounds__(BLOCK, 8)
void gae_pass1(const float* __restrict__ rew,
               const float* __restrict__ val,
               const float* __restrict__ don)
{
    const int n  = blockIdx.x * BLOCK + threadIdx.x;   // column
    const int k  = blockIdx.y;                         // time chunk
    const int lo = k * LCH;
    const int hi = lo + LCH - 1;

    float vn, dn;
    if (k == CT - 1) {
        vn = 0.0f; dn = 1.0f;
    } else {
        vn = val[(size_t)(hi + 1) * N_DIM + n];
        dn = don[(size_t)(hi + 1) * N_DIM + n];
    }

    float A = 0.0f, B = 1.0f;

    #pragma unroll
    for (int t = hi; t >= lo; --t) {
        const size_t idx = (size_t)t * N_DIM + n;
        const float rt = rew[idx];
        const float vt = val[idx];
        const float dt = don[idx];

        const float nt    = 1.0f - dn;
        const float delta = fmaf(GAMMA_F * nt, vn, rt) - vt;
        const float c     = GL_F * nt;

        A = fmaf(c, A, delta);
        B = c * B;

        vn = vt;
        dn = dt;
    }

    g_AB[(size_t)k * N_DIM + n] = make_float2(A, B);
}

// ---------------------------------------------------------------------------
// Mid: per-column reverse fold over CT chunk aggregates -> carry per chunk.
// Loads are address-independent across k; only the FMA chain is serial.
// ---------------------------------------------------------------------------
__global__ __launch_bounds__(BLOCK)
void gae_mid()
{
    const int n = blockIdx.x * BLOCK + threadIdx.x;

    float carry = 0.0f;
    #pragma unroll 8
    for (int k = CT - 1; k >= 0; --k) {
        const size_t idx = (size_t)k * N_DIM + n;
        g_carry[idx] = carry;
        const float2 ab = g_AB[idx];
        carry = fmaf(ab.y, carry, ab.x);
    }
}

// ---------------------------------------------------------------------------
// Pass 2: re-scan each chunk seeded with its carry; emit adv & returns.
// Reads use last-use hint; writes stream (evict-first) to preserve the
// L2-resident inputs loaded by pass 1.
// ---------------------------------------------------------------------------
__global__ __launch_bounds__(BLOCK, 8)
void gae_pass2(const float* __restrict__ rew,
               const float* __restrict__ val,
               const float* __restrict__ don,
               float* __restrict__ out)
{
    const int n  = blockIdx.x * BLOCK + threadIdx.x;
    const int k  = blockIdx.y;
    const int lo = k * LCH;
    const int hi = lo + LCH - 1;

    float vn, dn;
    if (k == CT - 1) {
        vn = 0.0f; dn = 1.0f;
    } else {
        vn = __ldcs(&val[(size_t)(hi + 1) * N_DIM + n]);
        dn = __ldcs(&don[(size_t)(hi + 1) * N_DIM + n]);
    }

    float adv = g_carry[(size_t)k * N_DIM + n];

    float* __restrict__ out_adv = out;
    float* __restrict__ out_ret = out + (size_t)T_DIM * N_DIM;

    #pragma unroll
    for (int t = hi; t >= lo; --t) {
        const size_t idx = (size_t)t * N_DIM + n;
        const float rt = __ldcs(&rew[idx]);
        const float vt = __ldcs(&val[idx]);
        const float dt = __ldcs(&don[idx]);

        const float nt    = 1.0f - dn;
        const float delta = fmaf(GAMMA_F * nt, vn, rt) - vt;
        const float c     = GL_F * nt;

        adv = fmaf(c, adv, delta);

        __stcs(&out_adv[idx], adv);
        __stcs(&out_ret[idx], adv + vt);

        vn = vt;
        dn = dt;
    }
}

// ---------------------------------------------------------------------------
extern "C" void kernel_launch(void* const* d_in, const int* in_sizes, int n_in,
                              void* d_out, int out_size)
{
    const float* rew = (const float*)d_in[0];
    const float* val = (const float*)d_in[1];
    const float* don = (const float*)d_in[2];
    float* out = (float*)d_out;

    dim3 block(BLOCK);
    dim3 grid(NGRP, CT);          // 16 x 128 = 2048 blocks

    gae_pass1<<<grid, block>>>(rew, val, don);
    gae_mid<<<N_DIM / BLOCK, block>>>();
    gae_pass2<<<grid, block>>>(rew, val, don, out);
}

// round 7
// speedup vs baseline: 1.1980x; 1.1980x over previous
#include <cuda_runtime.h>

// GAE reverse scan, 3-pass chunked linear recurrence.
//   adv_t = delta_t + c_t * adv_{t+1},  c_t = GL*(1-done_{t+1})
//   delta_t = r_t + GAMMA*v_{t+1}*(1-done_{t+1}) - v_t   (v_T=0, done_T=1)
// Output: d_out[0:T*N] = advantages, d_out[T*N:2*T*N] = advantages + values.
//
// R7: inputs (100 MB) fit in L2 (126 MB). Keep them resident across the
// replay loop by streaming the outputs out of L2 (__stcs, evict-first) and
// using DEFAULT load policy everywhere (R6's __ldcs poisoned residency).

#define T_DIM   2048
#define N_DIM   4096
#define CT      64                  // chunks in time
#define LCH     (T_DIM / CT)        // 32 rows per chunk
#define BLOCK   256
#define NGRP    (N_DIM / BLOCK)     // 16 column groups -> 1024 blocks

#define GAMMA_F 0.99f
#define GL_F    (0.99f * 0.95f)

// Scratch: per-(chunk, column) affine aggregate (A,B) and carries. 3 MB.
__device__ float2 g_AB   [CT * N_DIM];
__device__ float  g_carry[CT * N_DIM];

// ---------------------------------------------------------------------------
// Pass 1: per-chunk affine reduction. adv_top = A + B * carry_in.
// ---------------------------------------------------------------------------
__global__ __launch_bounds__(BLOCK, 8)
void gae_pass1(const float* __restrict__ rew,
               const float* __restrict__ val,
               const float* __restrict__ don)
{
    const int n  = blockIdx.x * BLOCK + threadIdx.x;   // column
    const int k  = blockIdx.y;                         // time chunk
    const int lo = k * LCH;
    const int hi = lo + LCH - 1;

    float vn, dn;
    if (k == CT - 1) {
        vn = 0.0f; dn = 1.0f;
    } else {
        vn = val[(size_t)(hi + 1) * N_DIM + n];
        dn = don[(size_t)(hi + 1) * N_DIM + n];
    }

    float A = 0.0f, B = 1.0f;

    #pragma unroll
    for (int t = hi; t >= lo; --t) {
        const size_t idx = (size_t)t * N_DIM + n;
        const float rt = rew[idx];
        const float vt = val[idx];
        const float dt = don[idx];

        const float nt    = 1.0f - dn;
        const float delta = fmaf(GAMMA_F * nt, vn, rt) - vt;
        const float c     = GL_F * nt;

        A = fmaf(c, A, delta);
        B = c * B;

        vn = vt;
        dn = dt;
    }

    g_AB[(size_t)k * N_DIM + n] = make_float2(A, B);
}

// ---------------------------------------------------------------------------
// Mid: per-column reverse fold over CT chunk aggregates -> carry per chunk.
// ---------------------------------------------------------------------------
__global__ __launch_bounds__(BLOCK)
void gae_mid()
{
    const int n = blockIdx.x * BLOCK + threadIdx.x;

    float carry = 0.0f;
    #pragma unroll 8
    for (int k = CT - 1; k >= 0; --k) {
        const size_t idx = (size_t)k * N_DIM + n;
        g_carry[idx] = carry;
        const float2 ab = g_AB[idx];
        carry = fmaf(ab.y, carry, ab.x);
    }
}

// ---------------------------------------------------------------------------
// Pass 2: re-scan each chunk seeded with its carry; emit adv & returns.
// Default loads (hit L2-resident inputs); evict-first streaming stores so
// outputs do not evict the inputs.
// ---------------------------------------------------------------------------
__global__ __launch_bounds__(BLOCK, 8)
void gae_pass2(const float* __restrict__ rew,
               const float* __restrict__ val,
               const float* __restrict__ don,
               float* __restrict__ out)
{
    const int n  = blockIdx.x * BLOCK + threadIdx.x;
    const int k  = blockIdx.y;
    const int lo = k * LCH;
    const int hi = lo + LCH - 1;

    float vn, dn;
    if (k == CT - 1) {
        vn = 0.0f; dn = 1.0f;
    } else {
        vn = val[(size_t)(hi + 1) * N_DIM + n];
        dn = don[(size_t)(hi + 1) * N_DIM + n];
    }

    float adv = g_carry[(size_t)k * N_DIM + n];

    float* __restrict__ out_adv = out;
    float* __restrict__ out_ret = out + (size_t)T_DIM * N_DIM;

    #pragma unroll
    for (int t = hi; t >= lo; --t) {
        const size_t idx = (size_t)t * N_DIM + n;
        const float rt = rew[idx];
        const float vt = val[idx];
        const float dt = don[idx];

        const float nt    = 1.0f - dn;
        const float delta = fmaf(GAMMA_F * nt, vn, rt) - vt;
        const float c     = GL_F * nt;

        adv = fmaf(c, adv, delta);

        __stcs(&out_adv[idx], adv);
        __stcs(&out_ret[idx], adv + vt);

        vn = vt;
        dn = dt;
    }
}

// ---------------------------------------------------------------------------
extern "C" void kernel_launch(void* const* d_in, const int* in_sizes, int n_in,
                              void* d_out, int out_size)
{
    const float* rew = (const float*)d_in[0];
    const float* val = (const float*)d_in[1];
    const float* don = (const float*)d_in[2];
    float* out = (float*)d_out;

    dim3 block(BLOCK);
    dim3 grid(NGRP, CT);          // 16 x 64 = 1024 blocks

    gae_pass1<<<grid, block>>>(rew, val, don);
    gae_mid<<<N_DIM / BLOCK, block>>>();
    gae_pass2<<<grid, block>>>(rew, val, don, out);
}